// round 10
// baseline (speedup 1.0000x reference)
#include <cuda_runtime.h>

// Problem constants
#define BB 256
#define TT 1024
#define VV 6
#define DD 64
#define UU 64
#define GG 256   // 4*U gate columns

// Precomputed per-vocab tables (V=6).
// Forward table PERMUTED for the 2-col/thread mapping: thread l (u=l>>1,
// p=l&1) owns cols {p*64+u, 128+p*64+u} and reads slots {2l, 2l+1} as LDS.64.
// Original col g (gi=g>>6, u=g&63) -> slot 4u + 2*(gi&1) + (gi>>1).
__device__ float g_xprojF[VV][GG];
__device__ float g_xprojB[VV][GG];   // unpermuted (epilogue indexes by gate)
__device__ int   g_maskv[VV];

__device__ __forceinline__ float sigmoid_fast(float x) {
    return __fdividef(1.f, 1.f + __expf(-x));
}
__device__ __forceinline__ float tanh_fast(float x) {
    return 2.f * __fdividef(1.f, 1.f + __expf(-2.f * x)) - 1.f;
}

__device__ __forceinline__ unsigned long long pack2(float lo, float hi) {
    unsigned long long r;
    asm("mov.b64 %0, {%1, %2};" : "=l"(r) : "f"(lo), "f"(hi));
    return r;
}
__device__ __forceinline__ void unpack2(unsigned long long v, float& lo, float& hi) {
    asm("mov.b64 {%0, %1}, %2;" : "=f"(lo), "=f"(hi) : "l"(v));
}
// Packed dual-FMA: lanes {lo,hi} independently (sm_10x FFMA2 path)
#define FMA2(d, a, b, c) \
    asm("fma.rn.f32x2 %0, %1, %2, %3;" : "=l"(d) : "l"(a), "l"(b), "l"(c))
#define ADD2(d, a, b) \
    asm("add.rn.f32x2 %0, %1, %2;" : "=l"(d) : "l"(a), "l"(b))

__global__ void precompute_kernel(const float* __restrict__ emb,
                                  const float* __restrict__ Wk_f,
                                  const float* __restrict__ b_f,
                                  const float* __restrict__ Wk_b,
                                  const float* __restrict__ b_b) {
    int v = blockIdx.x;
    int g = threadIdx.x;          // original gate column
    float sf = 0.f, sb = 0.f;
    #pragma unroll 8
    for (int k = 0; k < DD; k++) {
        float e = emb[v * DD + k];
        sf = fmaf(e, Wk_f[k * GG + g], sf);
        sb = fmaf(e, Wk_b[k * GG + g], sb);
    }
    int u = g & 63, gi = g >> 6;
    int slot = 4 * u + 2 * (gi & 1) + (gi >> 1);
    g_xprojF[v][slot] = sf + b_f[g];
    g_xprojB[v][g]    = sb + b_b[g];
    if (g == 0) {
        int m = 0;
        for (int k = 0; k < DD; k++) m |= (emb[v * DD + k] != 0.f);
        g_maskv[v] = m;
    }
}

// One LSTM step for ONE batch, executed by all 128 threads of the CTA.
// Inlined twice per time-step (once per batch); the two inlined bodies are
// fully independent, so ptxas interleaves batch1's FMA burst under batch0's
// activation/shuffle latency tail (static ILP — no reliance on the arbiter).
__device__ __forceinline__ void lstm_step(
    const float* __restrict__ hr, float* __restrict__ hw,
    const unsigned long long* __restrict__ wA,
    const unsigned long long* __restrict__ wB,
    float2 seed, int m, int p, int u, float& c, float& hprev)
{
    unsigned long long aA0 = pack2(seed.x, 0.f);
    unsigned long long aB0 = pack2(seed.y, 0.f);
    unsigned long long aA1 = 0ull, aA2 = 0ull, aA3 = 0ull;
    unsigned long long aB1 = 0ull, aB2 = 0ull, aB3 = 0ull;
    const ulonglong2* __restrict__ hp = (const ulonglong2*)hr;
    #pragma unroll
    for (int i = 0; i < 16; i += 2) {
        ulonglong2 pX = hp[i];       // {h4i,h4i+1},{h4i+2,h4i+3}
        ulonglong2 pY = hp[i + 1];
        FMA2(aA0, pX.x, wA[2 * i + 0], aA0);
        FMA2(aB0, pX.x, wB[2 * i + 0], aB0);
        FMA2(aA1, pX.y, wA[2 * i + 1], aA1);
        FMA2(aB1, pX.y, wB[2 * i + 1], aB1);
        FMA2(aA2, pY.x, wA[2 * i + 2], aA2);
        FMA2(aB2, pY.x, wB[2 * i + 2], aB2);
        FMA2(aA3, pY.y, wA[2 * i + 3], aA3);
        FMA2(aB3, pY.y, wB[2 * i + 3], aB3);
    }
    ADD2(aA0, aA0, aA1); ADD2(aA2, aA2, aA3); ADD2(aA0, aA0, aA2);
    ADD2(aB0, aB0, aB1); ADD2(aB2, aB2, aB3); ADD2(aB0, aB0, aB2);
    float zAl, zAh, zBl, zBh;
    unpack2(aA0, zAl, zAh); unpack2(aB0, zBl, zBh);
    float zA = zAl + zAh;            // i (p=0) or f (p=1)
    float zB = zBl + zBh;            // g (p=0) or o (p=1)
    float actA = sigmoid_fast(zA);
    float actB = (p == 0) ? tanh_fast(zB) : sigmoid_fast(zB);
    float ig = __shfl_xor_sync(0xffffffffu, actA * actB, 1);  // A->B: i*g
    if (p == 1) {
        float cn = fmaf(actA, c, ig);        // f*c + i*g
        float hn = actB * tanh_fast(cn);     // o * tanh(c)
        c     = m ? cn : c;
        hprev = m ? hn : hprev;
        hw[u] = hprev;
    }
}

// Grid 128 CTAs x 128 threads: 1 CTA/SM, 4 warps/SM = ONE warp per SMSP.
// Each thread runs its 2 gate columns for BOTH of the CTA's batches in one
// instruction stream (weights shared), so the two batches' chains overlap
// via static ILP. One __syncthreads per time-step covers both batches.
__global__ void __launch_bounds__(128, 1)
lstm_fwd_kernel(const int* __restrict__ tokens,
                const float* __restrict__ Wr_f,
                const float* __restrict__ Wd,
                const float* __restrict__ bd,
                float* __restrict__ out) {
    __shared__ float sh_xF[VV * GG];                 // 6 KB (permuted)
    __shared__ int   sh_tok[2][TT + 2];              // pad for prefetch
    __shared__ __align__(16) float sh_h[2][2][UU];   // [batch][parity][unit]
    __shared__ int   sh_mask[VV];
    __shared__ float sh_red[2][2];

    const int l    = threadIdx.x;        // 0..127
    const int b0   = blockIdx.x * 2;
    const int b1   = b0 + 1;
    const int u    = l >> 1;
    const int p    = l & 1;              // 0 = A{i,g}, 1 = B{f,o}
    const int colA = p * UU + u;         // i or f
    const int colB = 2 * UU + p * UU + u;// g or o
    const int lane = l & 31;

    // Recurrent weight columns as k-pairs (register-resident, shared by both batches).
    unsigned long long wA[32], wB[32];
    #pragma unroll
    for (int j = 0; j < 32; j++) {
        wA[j] = pack2(Wr_f[(2 * j) * GG + colA], Wr_f[(2 * j + 1) * GG + colA]);
        wB[j] = pack2(Wr_f[(2 * j) * GG + colB], Wr_f[(2 * j + 1) * GG + colB]);
    }

    // Stage tokens (both batches) and tables.
    for (int i = l; i < TT; i += 128) {
        sh_tok[0][i] = tokens[b0 * TT + i];
        sh_tok[1][i] = tokens[b1 * TT + i];
    }
    if (l == 0) { sh_tok[0][TT] = 0; sh_tok[0][TT + 1] = 0;
                  sh_tok[1][TT] = 0; sh_tok[1][TT + 1] = 0; }
    for (int i = l; i < VV * GG; i += 128) sh_xF[i] = (&g_xprojF[0][0])[i];
    if (l < VV) sh_mask[l] = g_maskv[l];
    if (l < UU) {
        sh_h[0][0][l] = 0.f; sh_h[0][1][l] = 0.f;
        sh_h[1][0][l] = 0.f; sh_h[1][1][l] = 0.f;
    }
    __syncthreads();

    float c0 = 0.f, hp0 = 0.f;   // batch0 cell/hidden state (B threads)
    float c1 = 0.f, hp1 = 0.f;   // batch1

    // First-step prefetch (tables are init-constant).
    int    tok0 = sh_tok[0][0];
    int    tok1 = sh_tok[1][0];
    float2 sd0  = *(const float2*)&sh_xF[tok0 * GG + 2 * l];
    float2 sd1  = *(const float2*)&sh_xF[tok1 * GG + 2 * l];
    int    m0   = sh_mask[tok0];
    int    m1   = sh_mask[tok1];

    float* __restrict__ h0A = sh_h[0][0];
    float* __restrict__ h0B = sh_h[0][1];
    float* __restrict__ h1A = sh_h[1][0];
    float* __restrict__ h1B = sh_h[1][1];

    for (int s = 0; s < TT; s += 2) {
        // --- even step: read parity0, write parity1 (both batches) ---
        lstm_step(h0A, h0B, wA, wB, sd0, m0, p, u, c0, hp0);
        lstm_step(h1A, h1B, wA, wB, sd1, m1, p, u, c1, hp1);
        tok0 = sh_tok[0][s + 1];
        tok1 = sh_tok[1][s + 1];
        sd0  = *(const float2*)&sh_xF[tok0 * GG + 2 * l];
        sd1  = *(const float2*)&sh_xF[tok1 * GG + 2 * l];
        m0   = sh_mask[tok0];
        m1   = sh_mask[tok1];
        __syncthreads();
        // --- odd step: read parity1, write parity0 ---
        lstm_step(h0B, h0A, wA, wB, sd0, m0, p, u, c0, hp0);
        lstm_step(h1B, h1A, wA, wB, sd1, m1, p, u, c1, hp1);
        tok0 = sh_tok[0][s + 2];
        tok1 = sh_tok[1][s + 2];
        sd0  = *(const float2*)&sh_xF[tok0 * GG + 2 * l];
        sd1  = *(const float2*)&sh_xF[tok1 * GG + 2 * l];
        m0   = sh_mask[tok0];
        m1   = sh_mask[tok1];
        __syncthreads();
    }

    // Final forward h is in parity 0 (step 1023 wrote it).
    // Backward direction = its first step only (h0=c0=0): z = xprojB(x[T-1]),
    // c = i*g, h_b = o*tanh(c), masked -> 0.
    if (l < UU) {
        const int tL0 = sh_tok[0][TT - 1];
        const int tL1 = sh_tok[1][TT - 1];

        float ii0 = sigmoid_fast(g_xprojB[tL0][l]);
        float gg0 = tanh_fast  (g_xprojB[tL0][2 * UU + l]);
        float oo0 = sigmoid_fast(g_xprojB[tL0][3 * UU + l]);
        float hb0 = sh_mask[tL0] ? oo0 * tanh_fast(ii0 * gg0) : 0.f;

        float ii1 = sigmoid_fast(g_xprojB[tL1][l]);
        float gg1 = tanh_fast  (g_xprojB[tL1][2 * UU + l]);
        float oo1 = sigmoid_fast(g_xprojB[tL1][3 * UU + l]);
        float hb1 = sh_mask[tL1] ? oo1 * tanh_fast(ii1 * gg1) : 0.f;

        float ct0 = sh_h[0][0][l] * Wd[l] + hb0 * Wd[UU + l];
        float ct1 = sh_h[1][0][l] * Wd[l] + hb1 * Wd[UU + l];
        #pragma unroll
        for (int off = 16; off > 0; off >>= 1) {
            ct0 += __shfl_down_sync(0xffffffffu, ct0, off);
            ct1 += __shfl_down_sync(0xffffffffu, ct1, off);
        }
        if (lane == 0) {
            sh_red[0][l >> 5] = ct0;    // warps 0,1 hold l<64
            sh_red[1][l >> 5] = ct1;
        }
    }
    __syncthreads();
    if (l == 0) {
        out[b0] = sh_red[0][0] + sh_red[0][1] + bd[0];
        out[b1] = sh_red[1][0] + sh_red[1][1] + bd[0];
    }
}

// Input order (metadata): tokens, emb, Wk_f, Wr_f, b_f, Wk_b, Wr_b, b_b, Wd, bd
extern "C" void kernel_launch(void* const* d_in, const int* in_sizes, int n_in,
                              void* d_out, int out_size) {
    const int*   tokens = (const int*)  d_in[0];
    const float* emb    = (const float*)d_in[1];
    const float* Wk_f   = (const float*)d_in[2];
    const float* Wr_f   = (const float*)d_in[3];
    const float* b_f    = (const float*)d_in[4];
    const float* Wk_b   = (const float*)d_in[5];
    // d_in[6] = Wr_b: unused (backward recurrence collapses to step 1 from h0=0)
    const float* b_b    = (const float*)d_in[7];
    const float* Wd     = (const float*)d_in[8];
    const float* bd     = (const float*)d_in[9];
    float*       out    = (float*)d_out;

    precompute_kernel<<<VV, GG>>>(emb, Wk_f, b_f, Wk_b, b_b);
    lstm_fwd_kernel<<<BB / 2, 128>>>(tokens, Wr_f, Wd, bd, out);
}

// round 12
// speedup vs baseline: 1.4357x; 1.4357x over previous
#include <cuda_runtime.h>

// Problem constants
#define BB 256
#define TT 1024
#define VV 6
#define DD 64
#define UU 64
#define GG 256   // 4*U gate columns

// Precomputed per-vocab tables (V=6).
// Forward table PERMUTED for the 2-col/thread mapping: thread l (u=l>>1,
// p=l&1) owns cols {p*64+u, 128+p*64+u} and reads slots {2l, 2l+1} as LDS.64.
// Original col g (gi=g>>6, u=g&63) -> slot 4u + 2*(gi&1) + (gi>>1).
__device__ float g_xprojF[VV][GG];
__device__ float g_xprojB[VV][GG];   // unpermuted (epilogue indexes by gate)
__device__ int   g_maskv[VV];

__device__ __forceinline__ float sigmoid_fast(float x) {
    return __fdividef(1.f, 1.f + __expf(-x));
}
__device__ __forceinline__ float tanh_fast(float x) {
    return 2.f * __fdividef(1.f, 1.f + __expf(-2.f * x)) - 1.f;
}

__device__ __forceinline__ unsigned long long pack2(float lo, float hi) {
    unsigned long long r;
    asm("mov.b64 %0, {%1, %2};" : "=l"(r) : "f"(lo), "f"(hi));
    return r;
}
__device__ __forceinline__ void unpack2(unsigned long long v, float& lo, float& hi) {
    asm("mov.b64 {%0, %1}, %2;" : "=f"(lo), "=f"(hi) : "l"(v));
}
// Packed dual-FMA: lanes {lo,hi} independently (sm_10x FFMA2 path)
#define FMA2(d, a, b, c) \
    asm("fma.rn.f32x2 %0, %1, %2, %3;" : "=l"(d) : "l"(a), "l"(b), "l"(c))
#define ADD2(d, a, b) \
    asm("add.rn.f32x2 %0, %1, %2;" : "=l"(d) : "l"(a), "l"(b))

__global__ void precompute_kernel(const float* __restrict__ emb,
                                  const float* __restrict__ Wk_f,
                                  const float* __restrict__ b_f,
                                  const float* __restrict__ Wk_b,
                                  const float* __restrict__ b_b) {
    int v = blockIdx.x;
    int g = threadIdx.x;          // original gate column
    float sf = 0.f, sb = 0.f;
    #pragma unroll 8
    for (int k = 0; k < DD; k++) {
        float e = emb[v * DD + k];
        sf = fmaf(e, Wk_f[k * GG + g], sf);
        sb = fmaf(e, Wk_b[k * GG + g], sb);
    }
    int u = g & 63, gi = g >> 6;
    int slot = 4 * u + 2 * (gi & 1) + (gi >> 1);
    g_xprojF[v][slot] = sf + b_f[g];
    g_xprojB[v][g]    = sb + b_b[g];
    if (g == 0) {
        int m = 0;
        for (int k = 0; k < DD; k++) m |= (emb[v * DD + k] != 0.f);
        g_maskv[v] = m;
    }
}

// FUSED step: both batches advance one time-step in ONE statement-interleaved
// instruction stream. Every LDS / FMA2 / activation alternates batch0/batch1,
// so ptxas's list scheduler receives an already-overlapped stream: batch1's
// FMA burst fills batch0's MUFU/SHFL latency tail and vice versa.
__device__ __forceinline__ void lstm_step2(
    const float* __restrict__ hr0, float* __restrict__ hw0,
    const float* __restrict__ hr1, float* __restrict__ hw1,
    const unsigned long long* __restrict__ wA,
    const unsigned long long* __restrict__ wB,
    float2 sd0, float2 sd1, int m0, int m1, int p, int u,
    float& c0, float& hp0, float& c1, float& hp1)
{
    // 8 accumulators: [batch][col][chain]; seeds folded into chain 0.
    unsigned long long A00 = pack2(sd0.x, 0.f), A01 = 0ull;  // b0 colA (i/f)
    unsigned long long B00 = pack2(sd0.y, 0.f), B01 = 0ull;  // b0 colB (g/o)
    unsigned long long A10 = pack2(sd1.x, 0.f), A11 = 0ull;  // b1 colA
    unsigned long long B10 = pack2(sd1.y, 0.f), B11 = 0ull;  // b1 colB
    const ulonglong2* __restrict__ h0p = (const ulonglong2*)hr0;
    const ulonglong2* __restrict__ h1p = (const ulonglong2*)hr1;
    #pragma unroll
    for (int i = 0; i < 16; i += 2) {
        ulonglong2 x0 = h0p[i];       // b0 h k-pairs {2i, 2i+1}
        ulonglong2 x1 = h1p[i];       // b1
        ulonglong2 y0 = h0p[i + 1];   // b0 h k-pairs {2i+2, 2i+3}
        ulonglong2 y1 = h1p[i + 1];   // b1
        FMA2(A00, x0.x, wA[2 * i + 0], A00);
        FMA2(A10, x1.x, wA[2 * i + 0], A10);
        FMA2(B00, x0.x, wB[2 * i + 0], B00);
        FMA2(B10, x1.x, wB[2 * i + 0], B10);
        FMA2(A01, x0.y, wA[2 * i + 1], A01);
        FMA2(A11, x1.y, wA[2 * i + 1], A11);
        FMA2(B01, x0.y, wB[2 * i + 1], B01);
        FMA2(B11, x1.y, wB[2 * i + 1], B11);
        FMA2(A00, y0.x, wA[2 * i + 2], A00);
        FMA2(A10, y1.x, wA[2 * i + 2], A10);
        FMA2(B00, y0.x, wB[2 * i + 2], B00);
        FMA2(B10, y1.x, wB[2 * i + 2], B10);
        FMA2(A01, y0.y, wA[2 * i + 3], A01);
        FMA2(A11, y1.y, wA[2 * i + 3], A11);
        FMA2(B01, y0.y, wB[2 * i + 3], B01);
        FMA2(B11, y1.y, wB[2 * i + 3], B11);
    }
    ADD2(A00, A00, A01);
    ADD2(A10, A10, A11);
    ADD2(B00, B00, B01);
    ADD2(B10, B10, B11);
    float lo, hi, zA0, zB0, zA1, zB1;
    unpack2(A00, lo, hi); zA0 = lo + hi;   // b0: i or f
    unpack2(A10, lo, hi); zA1 = lo + hi;   // b1
    unpack2(B00, lo, hi); zB0 = lo + hi;   // b0: g or o
    unpack2(B10, lo, hi); zB1 = lo + hi;   // b1
    // Activations interleaved: b0 and b1 MUFU chains overlap.
    float aA0 = sigmoid_fast(zA0);
    float aA1 = sigmoid_fast(zA1);
    float aB0 = (p == 0) ? tanh_fast(zB0) : sigmoid_fast(zB0);
    float aB1 = (p == 0) ? tanh_fast(zB1) : sigmoid_fast(zB1);
    float ig0 = __shfl_xor_sync(0xffffffffu, aA0 * aB0, 1);  // A->B: i*g
    float ig1 = __shfl_xor_sync(0xffffffffu, aA1 * aB1, 1);
    if (p == 1) {
        float cn0 = fmaf(aA0, c0, ig0);      // f*c + i*g
        float cn1 = fmaf(aA1, c1, ig1);
        float hn0 = aB0 * tanh_fast(cn0);    // o * tanh(c)
        float hn1 = aB1 * tanh_fast(cn1);
        c0  = m0 ? cn0 : c0;
        c1  = m1 ? cn1 : c1;
        hp0 = m0 ? hn0 : hp0;
        hp1 = m1 ? hn1 : hp1;
        hw0[u] = hp0;
        hw1[u] = hp1;
    }
}

// Grid 128 CTAs x 128 threads: 1 CTA/SM (single uniform wave), 4 warps/SM =
// ONE warp per SMSP. Each thread runs its 2 gate columns for BOTH of the
// CTA's batches inside one fused, statement-interleaved stream (weights
// shared). One __syncthreads per time-step covers both batches.
__global__ void __launch_bounds__(128, 1)
lstm_fwd_kernel(const int* __restrict__ tokens,
                const float* __restrict__ Wr_f,
                const float* __restrict__ Wd,
                const float* __restrict__ bd,
                float* __restrict__ out) {
    __shared__ float sh_xF[VV * GG];                 // 6 KB (permuted)
    __shared__ int   sh_tok[2][TT + 2];              // pad for prefetch
    __shared__ __align__(16) float sh_h[2][2][UU];   // [batch][parity][unit]
    __shared__ int   sh_mask[VV];
    __shared__ float sh_red[2][2];

    const int l    = threadIdx.x;        // 0..127
    const int b0   = blockIdx.x * 2;
    const int b1   = b0 + 1;
    const int u    = l >> 1;
    const int p    = l & 1;              // 0 = A{i,g}, 1 = B{f,o}
    const int colA = p * UU + u;         // i or f
    const int colB = 2 * UU + p * UU + u;// g or o
    const int lane = l & 31;

    // Recurrent weight columns as k-pairs (register-resident, shared by both batches).
    unsigned long long wA[32], wB[32];
    #pragma unroll
    for (int j = 0; j < 32; j++) {
        wA[j] = pack2(Wr_f[(2 * j) * GG + colA], Wr_f[(2 * j + 1) * GG + colA]);
        wB[j] = pack2(Wr_f[(2 * j) * GG + colB], Wr_f[(2 * j + 1) * GG + colB]);
    }

    // Stage tokens (both batches) and tables.
    for (int i = l; i < TT; i += 128) {
        sh_tok[0][i] = tokens[b0 * TT + i];
        sh_tok[1][i] = tokens[b1 * TT + i];
    }
    if (l == 0) { sh_tok[0][TT] = 0; sh_tok[0][TT + 1] = 0;
                  sh_tok[1][TT] = 0; sh_tok[1][TT + 1] = 0; }
    for (int i = l; i < VV * GG; i += 128) sh_xF[i] = (&g_xprojF[0][0])[i];
    if (l < VV) sh_mask[l] = g_maskv[l];
    if (l < UU) {
        sh_h[0][0][l] = 0.f; sh_h[0][1][l] = 0.f;
        sh_h[1][0][l] = 0.f; sh_h[1][1][l] = 0.f;
    }
    __syncthreads();

    float c0 = 0.f, hp0 = 0.f;   // batch0 cell/hidden state (B threads)
    float c1 = 0.f, hp1 = 0.f;   // batch1

    // First-step prefetch (tables are init-constant).
    int    tok0 = sh_tok[0][0];
    int    tok1 = sh_tok[1][0];
    float2 sd0  = *(const float2*)&sh_xF[tok0 * GG + 2 * l];
    float2 sd1  = *(const float2*)&sh_xF[tok1 * GG + 2 * l];
    int    m0   = sh_mask[tok0];
    int    m1   = sh_mask[tok1];

    float* __restrict__ h0A = sh_h[0][0];
    float* __restrict__ h0B = sh_h[0][1];
    float* __restrict__ h1A = sh_h[1][0];
    float* __restrict__ h1B = sh_h[1][1];

    for (int s = 0; s < TT; s += 2) {
        // --- even step: read parity0, write parity1 (both batches, fused) ---
        lstm_step2(h0A, h0B, h1A, h1B, wA, wB, sd0, sd1, m0, m1, p, u,
                   c0, hp0, c1, hp1);
        tok0 = sh_tok[0][s + 1];
        tok1 = sh_tok[1][s + 1];
        sd0  = *(const float2*)&sh_xF[tok0 * GG + 2 * l];
        sd1  = *(const float2*)&sh_xF[tok1 * GG + 2 * l];
        m0   = sh_mask[tok0];
        m1   = sh_mask[tok1];
        __syncthreads();
        // --- odd step: read parity1, write parity0 ---
        lstm_step2(h0B, h0A, h1B, h1A, wA, wB, sd0, sd1, m0, m1, p, u,
                   c0, hp0, c1, hp1);
        tok0 = sh_tok[0][s + 2];
        tok1 = sh_tok[1][s + 2];
        sd0  = *(const float2*)&sh_xF[tok0 * GG + 2 * l];
        sd1  = *(const float2*)&sh_xF[tok1 * GG + 2 * l];
        m0   = sh_mask[tok0];
        m1   = sh_mask[tok1];
        __syncthreads();
    }

    // Final forward h is in parity 0 (step 1023 wrote it).
    // Backward direction = its first step only (h0=c0=0): z = xprojB(x[T-1]),
    // c = i*g, h_b = o*tanh(c), masked -> 0.
    if (l < UU) {
        const int tL0 = sh_tok[0][TT - 1];
        const int tL1 = sh_tok[1][TT - 1];

        float ii0 = sigmoid_fast(g_xprojB[tL0][l]);
        float gg0 = tanh_fast  (g_xprojB[tL0][2 * UU + l]);
        float oo0 = sigmoid_fast(g_xprojB[tL0][3 * UU + l]);
        float hb0 = sh_mask[tL0] ? oo0 * tanh_fast(ii0 * gg0) : 0.f;

        float ii1 = sigmoid_fast(g_xprojB[tL1][l]);
        float gg1 = tanh_fast  (g_xprojB[tL1][2 * UU + l]);
        float oo1 = sigmoid_fast(g_xprojB[tL1][3 * UU + l]);
        float hb1 = sh_mask[tL1] ? oo1 * tanh_fast(ii1 * gg1) : 0.f;

        float ct0 = sh_h[0][0][l] * Wd[l] + hb0 * Wd[UU + l];
        float ct1 = sh_h[1][0][l] * Wd[l] + hb1 * Wd[UU + l];
        #pragma unroll
        for (int off = 16; off > 0; off >>= 1) {
            ct0 += __shfl_down_sync(0xffffffffu, ct0, off);
            ct1 += __shfl_down_sync(0xffffffffu, ct1, off);
        }
        if (lane == 0) {
            sh_red[0][l >> 5] = ct0;    // warps 0,1 hold l<64
            sh_red[1][l >> 5] = ct1;
        }
    }
    __syncthreads();
    if (l == 0) {
        out[b0] = sh_red[0][0] + sh_red[0][1] + bd[0];
        out[b1] = sh_red[1][0] + sh_red[1][1] + bd[0];
    }
}

// Input order (metadata): tokens, emb, Wk_f, Wr_f, b_f, Wk_b, Wr_b, b_b, Wd, bd
extern "C" void kernel_launch(void* const* d_in, const int* in_sizes, int n_in,
                              void* d_out, int out_size) {
    const int*   tokens = (const int*)  d_in[0];
    const float* emb    = (const float*)d_in[1];
    const float* Wk_f   = (const float*)d_in[2];
    const float* Wr_f   = (const float*)d_in[3];
    const float* b_f    = (const float*)d_in[4];
    const float* Wk_b   = (const float*)d_in[5];
    // d_in[6] = Wr_b: unused (backward recurrence collapses to step 1 from h0=0)
    const float* b_b    = (const float*)d_in[7];
    const float* Wd     = (const float*)d_in[8];
    const float* bd     = (const float*)d_in[9];
    float*       out    = (float*)d_out;

    precompute_kernel<<<VV, GG>>>(emb, Wk_f, b_f, Wk_b, b_b);
    lstm_fwd_kernel<<<BB / 2, 128>>>(tokens, Wr_f, Wd, bd, out);
}